// round 7
// baseline (speedup 1.0000x reference)
#include <cuda_runtime.h>
#include <cuda_bf16.h>
#include <math.h>
#include <stdint.h>

// ---------------- problem constants ----------------
#define BSZ    2
#define CDIM   256
#define LIMG   4096
#define DI     512
#define DS     16
#define DR     16
#define NCHUNK 128
#define TCH    32
#define MROWS  8192

// ---------------- scratch ----------------
__device__ __nv_bfloat16 g_xT  [MROWS * CDIM];
__device__ __nv_bfloat16 g_wb1 [CDIM * CDIM];
__device__ __nv_bfloat16 g_wbin[2 * DI * CDIM];
__device__ __nv_bfloat16 g_wbo [CDIM * DI];
__device__ __nv_bfloat16 g_wb2 [CDIM * CDIM];
__device__ __nv_bfloat16 g_wxp [128 * DI];
__device__ __nv_bfloat16 g_wdt [DI * 32];
__device__ __nv_bfloat16 g_t0a [MROWS * CDIM];
__device__ __nv_bfloat16 g_t0b [MROWS * CDIM];
__device__ __nv_bfloat16 g_xz  [MROWS * 2 * DI];
__device__ __nv_bfloat16 g_ub  [MROWS * DI];
__device__ __nv_bfloat16 g_dtr [MROWS * 32];
__device__ __nv_bfloat16 g_dtb [MROWS * DI];
__device__ float         g_Bm  [MROWS * DS];
__device__ float         g_Cm  [MROWS * DS];
__device__ float         g_Hc  [BSZ * DI * NCHUNK * DS];
__device__ float         g_Dc  [BSZ * DI * NCHUNK];
__device__ float         g_hs  [BSZ * DI * NCHUNK * DS];
__device__ __nv_bfloat16 g_yb  [MROWS * DI];
__device__ __nv_bfloat16 g_t2b [MROWS * CDIM];

// ================= mma.sync bf16 NT GEMM =================
#define SMEM_BYTES 33536

__device__ __forceinline__ uint32_t swz(int r, int c) {
    return (uint32_t)((r << 6) + ((c ^ ((r >> 1) & 3)) << 4));
}

#define LDSM4(R0,R1,R2,R3,ADDR) \
    asm volatile("ldmatrix.sync.aligned.m8n8.x4.shared.b16 {%0,%1,%2,%3},[%4];" \
                 : "=r"(R0),"=r"(R1),"=r"(R2),"=r"(R3) : "r"(ADDR))

#define MMA16816(D,A,B) \
    asm volatile("mma.sync.aligned.m16n8k16.row.col.f32.bf16.bf16.f32 " \
                 "{%0,%1,%2,%3},{%4,%5,%6,%7},{%8,%9},{%0,%1,%2,%3};" \
                 : "+f"((D)[0]),"+f"((D)[1]),"+f"((D)[2]),"+f"((D)[3]) \
                 : "r"((A)[0]),"r"((A)[1]),"r"((A)[2]),"r"((A)[3]), \
                   "r"((B)[0]),"r"((B)[1]))

template<int OUTMODE>
__global__ void __launch_bounds__(256, 2) gemm_mma(
    const __nv_bfloat16* __restrict__ A, const __nv_bfloat16* __restrict__ W,
    const float* __restrict__ bias, const float* __restrict__ resid,
    void* __restrict__ outp, float* __restrict__ out2, float* __restrict__ out3,
    int M, int N, int K)
{
    extern __shared__ char smem[];
    uint32_t sb = (uint32_t)__cvta_generic_to_shared(smem);
    int tid = threadIdx.x, wid = tid >> 5, lane = tid & 31;
    int wm = wid & 3, wn = wid >> 2;
    int m0 = blockIdx.y * 128, n0 = blockIdx.x * 128;

    float d[2][8][4];
#pragma unroll
    for (int i = 0; i < 2; i++)
#pragma unroll
        for (int j = 0; j < 8; j++)
#pragma unroll
            for (int q = 0; q < 4; q++) d[i][j][q] = 0.f;

    const int KIT = K >> 5;
    auto load_stage = [&](int kc, int s) {
        const __nv_bfloat16* Ap = A + (size_t)m0 * K + (kc << 5);
        const __nv_bfloat16* Wp = W + (size_t)n0 * K + (kc << 5);
        uint32_t sA = sb + s * 16384;
        uint32_t sW = sA + 8192;
#pragma unroll
        for (int i = 0; i < 2; i++) {
            int idx = tid + (i << 8);
            int r = idx >> 2, c = idx & 3;
            uint32_t so = swz(r, c);
            asm volatile("cp.async.cg.shared.global [%0],[%1],16;"
                         :: "r"(sA + so), "l"(Ap + (size_t)r * K + (c << 3)));
            asm volatile("cp.async.cg.shared.global [%0],[%1],16;"
                         :: "r"(sW + so), "l"(Wp + (size_t)r * K + (c << 3)));
        }
    };

    load_stage(0, 0);
    asm volatile("cp.async.commit_group;");

    int rowin = lane & 7, jm = lane >> 3;
    for (int kc = 0; kc < KIT; kc++) {
        if (kc + 1 < KIT) load_stage(kc + 1, (kc + 1) & 1);
        asm volatile("cp.async.commit_group;");
        asm volatile("cp.async.wait_group 1;");
        __syncthreads();

        uint32_t sA = sb + (kc & 1) * 16384;
        uint32_t sW = sA + 8192;
#pragma unroll
        for (int ks = 0; ks < 2; ks++) {
            uint32_t a[2][4];
            int chunk = (ks << 1) + (jm >> 1);
#pragma unroll
            for (int mt = 0; mt < 2; mt++) {
                int row = (wm << 5) + (mt << 4) + ((jm & 1) << 3) + rowin;
                LDSM4(a[mt][0], a[mt][1], a[mt][2], a[mt][3], sA + swz(row, chunk));
            }
            uint32_t bq[8][2];
#pragma unroll
            for (int p = 0; p < 4; p++) {
                int row = (wn << 6) + (p << 4) + ((jm & 1) << 3) + rowin;
                uint32_t q0, q1, q2, q3;
                LDSM4(q0, q1, q2, q3, sW + swz(row, chunk));
                bq[2 * p][0] = q0; bq[2 * p + 1][0] = q1;
                bq[2 * p][1] = q2; bq[2 * p + 1][1] = q3;
            }
#pragma unroll
            for (int mt = 0; mt < 2; mt++)
#pragma unroll
                for (int nt = 0; nt < 8; nt++)
                    MMA16816(d[mt][nt], a[mt], bq[nt]);
        }
        __syncthreads();
    }

    float* stg = (float*)smem;
#pragma unroll
    for (int h = 0; h < 2; h++) {
        if (wn == h) {
#pragma unroll
            for (int mt = 0; mt < 2; mt++)
#pragma unroll
                for (int nt = 0; nt < 8; nt++)
#pragma unroll
                    for (int q = 0; q < 4; q++) {
                        int r  = (wm << 5) + (mt << 4) + (lane >> 2) + ((q >> 1) << 3);
                        int cc = (nt << 3) + ((lane & 3) << 1) + (q & 1);
                        stg[r * 65 + cc] = d[mt][nt][q];
                    }
        }
        __syncthreads();

        if (OUTMODE == 4) {
            if (h == 0) {
#pragma unroll
                for (int i = 0; i < 32; i++) {
                    int idx = (i << 8) + tid;
                    int cc = idx & 63, rw = idx >> 6;
                    float v = stg[rw * 65 + cc];
                    int row = m0 + rw;
                    __nv_bfloat16* dtr = (__nv_bfloat16*)outp;
                    if (cc < 16) dtr[(size_t)row * 32 + cc] = __float2bfloat16(v);
                    else if (cc < 32) { out2[(size_t)row * 16 + cc - 16] = v;
                                        dtr[(size_t)row * 32 + cc] = __float2bfloat16(0.f); }
                    else if (cc < 48) out3[(size_t)row * 16 + cc - 32] = v;
                }
            }
        } else if (OUTMODE == 2) {
            float* out = (float*)outp;
            int bI = m0 / LIMG, l0 = m0 % LIMG;
#pragma unroll
            for (int i = 0; i < 32; i++) {
                int idx = (i << 8) + tid;
                int rw = idx & 127, col = idx >> 7;
                float v = stg[rw * 65 + col] + bias[n0 + (h << 6) + col];
                size_t o = (size_t)(bI * N + n0 + (h << 6) + col) * LIMG + l0 + rw;
                out[o] = v + resid[o];
            }
        } else {
#pragma unroll
            for (int i = 0; i < 32; i++) {
                int idx = (i << 8) + tid;
                int cc = idx & 63, rw = idx >> 6;
                float v = stg[rw * 65 + cc];
                int col = n0 + (h << 6) + cc;
                if (OUTMODE == 3) {
                    float s = v + bias[col];
                    v = (s > 20.f) ? s : log1pf(expf(s));
                    ((__nv_bfloat16*)outp)[(size_t)(m0 + rw) * N + col] = __float2bfloat16(v);
                } else {
                    if (bias) v += bias[col];
                    if (OUTMODE == 1)
                        ((__nv_bfloat16*)outp)[(size_t)(m0 + rw) * N + col] = __float2bfloat16(v);
                    else
                        ((float*)outp)[(size_t)(m0 + rw) * N + col] = v;
                }
            }
        }
        __syncthreads();
    }
}

// ================= single fused weight-prep kernel =================
#define S_WB1  (CDIM*CDIM)
#define S_WBIN (2*DI*CDIM)
#define S_WBO  (CDIM*DI)
#define S_WB2  (CDIM*CDIM)
#define S_WXP  (128*DI)
#define S_WDT  (DI*32)
#define PREP_TOTAL (S_WB1+S_WBIN+S_WBO+S_WB2+S_WXP+S_WDT)
__global__ void __launch_bounds__(256) prep_weights(
    const float* __restrict__ cv1_w, const float* __restrict__ in_proj_w,
    const float* __restrict__ out_proj_w, const float* __restrict__ cv2_w,
    const float* __restrict__ x_proj_w, const float* __restrict__ dt_proj_w,
    __nv_bfloat16* __restrict__ wb1, __nv_bfloat16* __restrict__ wbin,
    __nv_bfloat16* __restrict__ wbo, __nv_bfloat16* __restrict__ wb2,
    __nv_bfloat16* __restrict__ wxp, __nv_bfloat16* __restrict__ wdt)
{
    int i = blockIdx.x * 256 + threadIdx.x;
    if (i < S_WB1) { wb1[i] = __float2bfloat16(cv1_w[i]); return; }
    i -= S_WB1;
    if (i < S_WBIN) { wbin[i] = __float2bfloat16(in_proj_w[i]); return; }
    i -= S_WBIN;
    if (i < S_WBO) { wbo[i] = __float2bfloat16(out_proj_w[i]); return; }
    i -= S_WBO;
    if (i < S_WB2) { wb2[i] = __float2bfloat16(cv2_w[i]); return; }
    i -= S_WB2;
    if (i < S_WXP) {
        int r = i >> 9, c = i & 511;
        wxp[i] = __float2bfloat16(r < 48 ? x_proj_w[r * DI + c] : 0.f);
        return;
    }
    i -= S_WXP;
    if (i < S_WDT) {
        int r = i >> 5, c = i & 31;
        wdt[i] = __float2bfloat16(c < 16 ? dt_proj_w[r * DR + c] : 0.f);
    }
}

// NCHW x -> row-major bf16 [b*L + l][c]
__global__ void __launch_bounds__(256) xpose(const float* __restrict__ x,
                                             __nv_bfloat16* __restrict__ xT)
{
    __shared__ float t[32][33];
    int l0 = blockIdx.x << 5, c0 = blockIdx.y << 5, b = blockIdx.z;
    int tx = threadIdx.x, ty = threadIdx.y;
#pragma unroll
    for (int j = 0; j < 32; j += 8)
        t[ty + j][tx] = x[((size_t)(b * CDIM + c0 + ty + j)) * LIMG + l0 + tx];
    __syncthreads();
#pragma unroll
    for (int j = 0; j < 32; j += 8)
        xT[((size_t)(b * LIMG + l0 + ty + j)) * CDIM + c0 + tx] = __float2bfloat16(t[tx][ty + j]);
}

// ================= LayerNorm: warp per row, vectorized =================
__global__ void __launch_bounds__(256) ln_kernel(
    const __nv_bfloat16* __restrict__ t0, __nv_bfloat16* __restrict__ t0b,
    const float* __restrict__ gam, const float* __restrict__ bet)
{
    int wid  = threadIdx.x >> 5, lane = threadIdx.x & 31;
    int m    = blockIdx.x * 8 + wid;
    const __nv_bfloat16* row = t0 + (size_t)m * CDIM + lane * 8;
    uint4 pk = *(const uint4*)row;
    __nv_bfloat16 vb[8];
    *(uint4*)vb = pk;
    float v[8], s1 = 0.f, s2 = 0.f;
#pragma unroll
    for (int j = 0; j < 8; j++) {
        v[j] = __bfloat162float(vb[j]);
        s1 += v[j];
        s2 += v[j] * v[j];
    }
#pragma unroll
    for (int off = 16; off; off >>= 1) {
        s1 += __shfl_xor_sync(0xffffffffu, s1, off);
        s2 += __shfl_xor_sync(0xffffffffu, s2, off);
    }
    float mu = s1 * (1.f / CDIM);
    float rs = rsqrtf(s2 * (1.f / CDIM) - mu * mu + 1e-5f);
    float4 g0 = *(const float4*)(gam + lane * 8);
    float4 g1 = *(const float4*)(gam + lane * 8 + 4);
    float4 b0 = *(const float4*)(bet + lane * 8);
    float4 b1 = *(const float4*)(bet + lane * 8 + 4);
    float gg[8] = {g0.x, g0.y, g0.z, g0.w, g1.x, g1.y, g1.z, g1.w};
    float bb[8] = {b0.x, b0.y, b0.z, b0.w, b1.x, b1.y, b1.z, b1.w};
    __nv_bfloat16 ob[8];
#pragma unroll
    for (int j = 0; j < 8; j++)
        ob[j] = __float2bfloat16((v[j] - mu) * rs * gg[j] + bb[j]);
    *(uint4*)(t0b + (size_t)m * CDIM + lane * 8) = *(uint4*)ob;
}

// ================= sliding-window depthwise conv + SiLU =================
#define CLSEG 16
__global__ void __launch_bounds__(512) conv_silu_kernel(
    const __nv_bfloat16* __restrict__ xz, const float* __restrict__ cw,
    const float* __restrict__ cb, __nv_bfloat16* __restrict__ ub)
{
    int b = blockIdx.y, d = threadIdx.x;
    int l0 = blockIdx.x * CLSEG;
    float w0 = cw[d * 4 + 0], w1 = cw[d * 4 + 1], w2 = cw[d * 4 + 2], w3 = cw[d * 4 + 3];
    float bia = cb[d];
    size_t rb = (size_t)(b * LIMG) * (2 * DI) + d;
    float x0 = (l0 >= 3) ? __bfloat162float(xz[rb + (size_t)(l0 - 3) * (2 * DI)]) : 0.f;
    float x1 = (l0 >= 2) ? __bfloat162float(xz[rb + (size_t)(l0 - 2) * (2 * DI)]) : 0.f;
    float x2 = (l0 >= 1) ? __bfloat162float(xz[rb + (size_t)(l0 - 1) * (2 * DI)]) : 0.f;
#pragma unroll
    for (int i = 0; i < CLSEG; i++) {
        float x3 = __bfloat162float(xz[rb + (size_t)(l0 + i) * (2 * DI)]);
        float s = bia + w0 * x0 + w1 * x1 + w2 * x2 + w3 * x3;
        float sig = 1.f / (1.f + __expf(-s));
        ub[(size_t)(b * LIMG + l0 + i) * DI + d] = __float2bfloat16(s * sig);
        x0 = x1; x1 = x2; x2 = x3;
    }
}

// ================= chunked selective scan =================
__global__ void __launch_bounds__(512) scan_phase1(
    const __nv_bfloat16* __restrict__ dt, const __nv_bfloat16* __restrict__ u,
    const float* __restrict__ Bm, const float* __restrict__ A_log,
    float* __restrict__ Hc, float* __restrict__ Dc)
{
    __shared__ float Bs[TCH][DS];
    int c = blockIdx.x, b = blockIdx.y, d = threadIdx.x;
    for (int idx = d; idx < TCH * DS; idx += 512)
        Bs[idx >> 4][idx & 15] = Bm[(size_t)(b * LIMG + c * TCH) * DS + idx];
    __syncthreads();

    float A[DS], h[DS];
    bool fast = true;
#pragma unroll
    for (int n = 0; n < DS; n++) {
        A[n] = -expf(A_log[d * DS + n]);
        h[n] = 0.f;
        fast = fast && (fabsf(A[n] + (float)(n + 1)) < 1e-3f * (n + 1));
    }
    float S = 0.f;
    size_t base = (size_t)(b * LIMG + c * TCH) * DI + d;
    if (fast) {
        for (int i = 0; i < TCH; i++) {
            float dtv = __bfloat162float(dt[base + (size_t)i * DI]);
            float uv  = __bfloat162float(u [base + (size_t)i * DI]);
            float du  = dtv * uv;
            S += dtv;
            float w = __expf(-dtv), e = 1.f;
#pragma unroll
            for (int n = 0; n < DS; n++) {
                e *= w;
                h[n] = e * h[n] + du * Bs[i][n];
            }
        }
    } else {
        for (int i = 0; i < TCH; i++) {
            float dtv = __bfloat162float(dt[base + (size_t)i * DI]);
            float uv  = __bfloat162float(u [base + (size_t)i * DI]);
            float du  = dtv * uv;
            S += dtv;
#pragma unroll
            for (int n = 0; n < DS; n++)
                h[n] = __expf(dtv * A[n]) * h[n] + du * Bs[i][n];
        }
    }
    size_t o = ((size_t)(b * DI + d) * NCHUNK + c) * DS;
#pragma unroll
    for (int n = 0; n < DS; n++) Hc[o + n] = h[n];
    Dc[(b * DI + d) * NCHUNK + c] = S;
}

__global__ void __launch_bounds__(256) scan_phase2(
    const float* __restrict__ Hc, const float* __restrict__ Dc,
    const float* __restrict__ A_log, float* __restrict__ hstart)
{
    int gw   = (blockIdx.x * 256 + threadIdx.x) >> 5;
    int lane = threadIdx.x & 31;
    int n    = lane & 15;
    int d    = gw & (DI - 1);
    float An = -expf(A_log[d * DS + n]);
    float hs = 0.f;
    size_t bb = (size_t)gw * NCHUNK;
    for (int c = 0; c < NCHUNK; c++) {
        if (lane < 16) hstart[(bb + c) * DS + n] = hs;
        float Hv = Hc[(bb + c) * DS + n];
        float Dv = Dc[bb + c];
        hs = __expf(An * Dv) * hs + Hv;
    }
}

__global__ void __launch_bounds__(512) scan_phase3(
    const __nv_bfloat16* __restrict__ dt, const __nv_bfloat16* __restrict__ u,
    const float* __restrict__ Bm, const float* __restrict__ Cm,
    const float* __restrict__ A_log, const float* __restrict__ Dpar,
    const __nv_bfloat16* __restrict__ xz, const float* __restrict__ hstart,
    __nv_bfloat16* __restrict__ yb)
{
    __shared__ float Bs[TCH][DS], Cs[TCH][DS];
    int c = blockIdx.x, b = blockIdx.y, d = threadIdx.x;
    for (int idx = d; idx < TCH * DS; idx += 512) {
        size_t g = (size_t)(b * LIMG + c * TCH) * DS + idx;
        Bs[idx >> 4][idx & 15] = Bm[g];
        Cs[idx >> 4][idx & 15] = Cm[g];
    }
    __syncthreads();

    float A[DS], h[DS];
    bool fast = true;
    size_t ho = ((size_t)(b * DI + d) * NCHUNK + c) * DS;
#pragma unroll
    for (int n = 0; n < DS; n++) {
        A[n] = -expf(A_log[d * DS + n]);
        h[n] = hstart[ho + n];
        fast = fast && (fabsf(A[n] + (float)(n + 1)) < 1e-3f * (n + 1));
    }
    float Dd = Dpar[d];
    size_t base  = (size_t)(b * LIMG + c * TCH) * DI + d;
    size_t basez = (size_t)(b * LIMG + c * TCH) * (2 * DI) + DI + d;
    for (int i = 0; i < TCH; i++) {
        float dtv = __bfloat162float(dt[base + (size_t)i * DI]);
        float uv  = __bfloat162float(u [base + (size_t)i * DI]);
        float du  = dtv * uv;
        float acc = 0.f;
        if (fast) {
            float w = __expf(-dtv), e = 1.f;
#pragma unroll
            for (int n = 0; n < DS; n++) {
                e *= w;
                h[n] = e * h[n] + du * Bs[i][n];
                acc += h[n] * Cs[i][n];
            }
        } else {
#pragma unroll
            for (int n = 0; n < DS; n++) {
                h[n] = __expf(dtv * A[n]) * h[n] + du * Bs[i][n];
                acc += h[n] * Cs[i][n];
            }
        }
        float zv  = __bfloat162float(xz[basez + (size_t)i * (2 * DI)]);
        float sig = 1.f / (1.f + __expf(-zv));
        float yy  = (acc + uv * Dd) * (zv * sig);
        yb[base + (size_t)i * DI] = __float2bfloat16(yy);
    }
}

// ================= launch =================
extern "C" void kernel_launch(void* const* d_in, const int* in_sizes, int n_in,
                              void* d_out, int out_size)
{
    (void)in_sizes; (void)n_in; (void)out_size;
    const float* x         = (const float*)d_in[0];
    const float* cv1_w     = (const float*)d_in[1];
    const float* cv1_b     = (const float*)d_in[2];
    const float* ln_g      = (const float*)d_in[3];
    const float* ln_b      = (const float*)d_in[4];
    const float* in_proj_w = (const float*)d_in[5];
    const float* conv_w    = (const float*)d_in[6];
    const float* conv_b    = (const float*)d_in[7];
    const float* x_proj_w  = (const float*)d_in[8];
    const float* dt_proj_w = (const float*)d_in[9];
    const float* dt_proj_b = (const float*)d_in[10];
    const float* A_log     = (const float*)d_in[11];
    const float* Dp        = (const float*)d_in[12];
    const float* out_proj_w= (const float*)d_in[13];
    const float* cv2_w     = (const float*)d_in[14];
    const float* cv2_b     = (const float*)d_in[15];
    float* out = (float*)d_out;

    __nv_bfloat16 *xT, *wb1, *wbin, *wbo, *wb2, *wxp, *wdt;
    __nv_bfloat16 *t0a, *t0b, *xz, *ub, *dtr, *dtb, *yb, *t2b;
    float *Bm, *Cm, *Hc, *Dc, *hs;
    cudaGetSymbolAddress((void**)&xT,  g_xT);
    cudaGetSymbolAddress((void**)&wb1, g_wb1);
    cudaGetSymbolAddress((void**)&wbin,g_wbin);
    cudaGetSymbolAddress((void**)&wbo, g_wbo);
    cudaGetSymbolAddress((void**)&wb2, g_wb2);
    cudaGetSymbolAddress((void**)&wxp, g_wxp);
    cudaGetSymbolAddress((void**)&wdt, g_wdt);
    cudaGetSymbolAddress((void**)&t0a, g_t0a);
    cudaGetSymbolAddress((void**)&t0b, g_t0b);
    cudaGetSymbolAddress((void**)&xz,  g_xz);
    cudaGetSymbolAddress((void**)&ub,  g_ub);
    cudaGetSymbolAddress((void**)&dtr, g_dtr);
    cudaGetSymbolAddress((void**)&dtb, g_dtb);
    cudaGetSymbolAddress((void**)&Bm,  g_Bm);
    cudaGetSymbolAddress((void**)&Cm,  g_Cm);
    cudaGetSymbolAddress((void**)&Hc,  g_Hc);
    cudaGetSymbolAddress((void**)&Dc,  g_Dc);
    cudaGetSymbolAddress((void**)&hs,  g_hs);
    cudaGetSymbolAddress((void**)&yb,  g_yb);
    cudaGetSymbolAddress((void**)&t2b, g_t2b);

    prep_weights<<<(PREP_TOTAL + 255)/256, 256>>>(
        cv1_w, in_proj_w, out_proj_w, cv2_w, x_proj_w, dt_proj_w,
        wb1, wbin, wbo, wb2, wxp, wdt);
    xpose<<<dim3(LIMG/32, CDIM/32, BSZ), dim3(32, 8)>>>(x, xT);

    gemm_mma<1><<<dim3(CDIM/128, MROWS/128), 256, SMEM_BYTES>>>(
        xT, wb1, cv1_b, nullptr, t0a, nullptr, nullptr, MROWS, CDIM, CDIM);
    ln_kernel<<<MROWS/8, 256>>>(t0a, t0b, ln_g, ln_b);
    gemm_mma<1><<<dim3(2*DI/128, MROWS/128), 256, SMEM_BYTES>>>(
        t0b, wbin, nullptr, nullptr, xz, nullptr, nullptr, MROWS, 2*DI, CDIM);
    conv_silu_kernel<<<dim3(LIMG/CLSEG, BSZ), 512>>>(xz, conv_w, conv_b, ub);
    gemm_mma<4><<<dim3(1, MROWS/128), 256, SMEM_BYTES>>>(
        ub, wxp, nullptr, nullptr, dtr, Bm, Cm, MROWS, 128, DI);
    gemm_mma<3><<<dim3(DI/128, MROWS/128), 256, SMEM_BYTES>>>(
        dtr, wdt, dt_proj_b, nullptr, dtb, nullptr, nullptr, MROWS, DI, 32);
    scan_phase1<<<dim3(NCHUNK, BSZ), 512>>>(dtb, ub, Bm, A_log, Hc, Dc);
    scan_phase2<<<(BSZ*DI)/8, 256>>>(Hc, Dc, A_log, hs);
    scan_phase3<<<dim3(NCHUNK, BSZ), 512>>>(dtb, ub, Bm, Cm, A_log, Dp, xz, hs, yb);
    gemm_mma<1><<<dim3(CDIM/128, MROWS/128), 256, SMEM_BYTES>>>(
        yb, wbo, nullptr, nullptr, t2b, nullptr, nullptr, MROWS, CDIM, DI);
    gemm_mma<2><<<dim3(CDIM/128, MROWS/128), 256, SMEM_BYTES>>>(
        t2b, wb2, cv2_b, x, out, nullptr, nullptr, MROWS, CDIM, CDIM);
}

// round 8
// speedup vs baseline: 1.3756x; 1.3756x over previous
#include <cuda_runtime.h>
#include <cuda_bf16.h>
#include <math.h>
#include <stdint.h>

// ---------------- problem constants ----------------
#define BSZ    2
#define CDIM   256
#define LIMG   4096
#define DI     512
#define DS     16
#define DR     16
#define NCHUNK 64
#define TCH    64
#define MROWS  8192

// ---------------- scratch ----------------
__device__ __nv_bfloat16 g_xT  [MROWS * CDIM];
__device__ __nv_bfloat16 g_wb1 [CDIM * CDIM];
__device__ __nv_bfloat16 g_wbin[2 * DI * CDIM];
__device__ __nv_bfloat16 g_wbo [CDIM * DI];
__device__ __nv_bfloat16 g_wb2 [CDIM * CDIM];
__device__ __nv_bfloat16 g_wxp [128 * DI];
__device__ __nv_bfloat16 g_wdt [DI * 32];
__device__ __nv_bfloat16 g_t0a [MROWS * CDIM];
__device__ __nv_bfloat16 g_t0b [MROWS * CDIM];
__device__ __nv_bfloat16 g_xz  [MROWS * 2 * DI];
__device__ __nv_bfloat16 g_ub  [MROWS * DI];
__device__ __nv_bfloat16 g_dtr [MROWS * 32];
__device__ __nv_bfloat16 g_dtb [MROWS * DI];
__device__ float         g_Bm  [MROWS * DS];
__device__ float         g_Cm  [MROWS * DS];
__device__ float         g_Hc  [BSZ * DI * NCHUNK * DS];
__device__ float         g_Dc  [BSZ * DI * NCHUNK];
__device__ float         g_hs  [BSZ * DI * NCHUNK * DS];
__device__ __nv_bfloat16 g_yb  [MROWS * DI];
__device__ __nv_bfloat16 g_t2b [MROWS * CDIM];

// ================= mma.sync bf16 NT GEMM =================
#define SMEM_BYTES 33536

__device__ __forceinline__ uint32_t swz(int r, int c) {
    return (uint32_t)((r << 6) + ((c ^ ((r >> 1) & 3)) << 4));
}

#define LDSM4(R0,R1,R2,R3,ADDR) \
    asm volatile("ldmatrix.sync.aligned.m8n8.x4.shared.b16 {%0,%1,%2,%3},[%4];" \
                 : "=r"(R0),"=r"(R1),"=r"(R2),"=r"(R3) : "r"(ADDR))

#define MMA16816(D,A,B) \
    asm volatile("mma.sync.aligned.m16n8k16.row.col.f32.bf16.bf16.f32 " \
                 "{%0,%1,%2,%3},{%4,%5,%6,%7},{%8,%9},{%0,%1,%2,%3};" \
                 : "+f"((D)[0]),"+f"((D)[1]),"+f"((D)[2]),"+f"((D)[3]) \
                 : "r"((A)[0]),"r"((A)[1]),"r"((A)[2]),"r"((A)[3]), \
                   "r"((B)[0]),"r"((B)[1]))

template<int OUTMODE>
__global__ void __launch_bounds__(256, 2) gemm_mma(
    const __nv_bfloat16* __restrict__ A, const __nv_bfloat16* __restrict__ W,
    const float* __restrict__ bias, const float* __restrict__ resid,
    void* __restrict__ outp, float* __restrict__ out2, float* __restrict__ out3,
    int M, int N, int K)
{
    extern __shared__ char smem[];
    uint32_t sb = (uint32_t)__cvta_generic_to_shared(smem);
    int tid = threadIdx.x, wid = tid >> 5, lane = tid & 31;
    int wm = wid & 3, wn = wid >> 2;
    int m0 = blockIdx.y * 128, n0 = blockIdx.x * 128;

    float d[2][8][4];
#pragma unroll
    for (int i = 0; i < 2; i++)
#pragma unroll
        for (int j = 0; j < 8; j++)
#pragma unroll
            for (int q = 0; q < 4; q++) d[i][j][q] = 0.f;

    const int KIT = K >> 5;
    auto load_stage = [&](int kc, int s) {
        const __nv_bfloat16* Ap = A + (size_t)m0 * K + (kc << 5);
        const __nv_bfloat16* Wp = W + (size_t)n0 * K + (kc << 5);
        uint32_t sA = sb + s * 16384;
        uint32_t sW = sA + 8192;
#pragma unroll
        for (int i = 0; i < 2; i++) {
            int idx = tid + (i << 8);
            int r = idx >> 2, c = idx & 3;
            uint32_t so = swz(r, c);
            asm volatile("cp.async.cg.shared.global [%0],[%1],16;"
                         :: "r"(sA + so), "l"(Ap + (size_t)r * K + (c << 3)));
            asm volatile("cp.async.cg.shared.global [%0],[%1],16;"
                         :: "r"(sW + so), "l"(Wp + (size_t)r * K + (c << 3)));
        }
    };

    load_stage(0, 0);
    asm volatile("cp.async.commit_group;");

    int rowin = lane & 7, jm = lane >> 3;
    for (int kc = 0; kc < KIT; kc++) {
        if (kc + 1 < KIT) load_stage(kc + 1, (kc + 1) & 1);
        asm volatile("cp.async.commit_group;");
        asm volatile("cp.async.wait_group 1;");
        __syncthreads();

        uint32_t sA = sb + (kc & 1) * 16384;
        uint32_t sW = sA + 8192;
#pragma unroll
        for (int ks = 0; ks < 2; ks++) {
            uint32_t a[2][4];
            int chunk = (ks << 1) + (jm >> 1);
#pragma unroll
            for (int mt = 0; mt < 2; mt++) {
                int row = (wm << 5) + (mt << 4) + ((jm & 1) << 3) + rowin;
                LDSM4(a[mt][0], a[mt][1], a[mt][2], a[mt][3], sA + swz(row, chunk));
            }
            uint32_t bq[8][2];
#pragma unroll
            for (int p = 0; p < 4; p++) {
                int row = (wn << 6) + (p << 4) + ((jm & 1) << 3) + rowin;
                uint32_t q0, q1, q2, q3;
                LDSM4(q0, q1, q2, q3, sW + swz(row, chunk));
                bq[2 * p][0] = q0; bq[2 * p + 1][0] = q1;
                bq[2 * p][1] = q2; bq[2 * p + 1][1] = q3;
            }
#pragma unroll
            for (int mt = 0; mt < 2; mt++)
#pragma unroll
                for (int nt = 0; nt < 8; nt++)
                    MMA16816(d[mt][nt], a[mt], bq[nt]);
        }
        __syncthreads();
    }

    float* stg = (float*)smem;
#pragma unroll
    for (int h = 0; h < 2; h++) {
        if (wn == h) {
#pragma unroll
            for (int mt = 0; mt < 2; mt++)
#pragma unroll
                for (int nt = 0; nt < 8; nt++)
#pragma unroll
                    for (int q = 0; q < 4; q++) {
                        int r  = (wm << 5) + (mt << 4) + (lane >> 2) + ((q >> 1) << 3);
                        int cc = (nt << 3) + ((lane & 3) << 1) + (q & 1);
                        stg[r * 65 + cc] = d[mt][nt][q];
                    }
        }
        __syncthreads();

        if (OUTMODE == 4) {
            if (h == 0) {
#pragma unroll
                for (int i = 0; i < 32; i++) {
                    int idx = (i << 8) + tid;
                    int cc = idx & 63, rw = idx >> 6;
                    float v = stg[rw * 65 + cc];
                    int row = m0 + rw;
                    __nv_bfloat16* dtr = (__nv_bfloat16*)outp;
                    if (cc < 16) dtr[(size_t)row * 32 + cc] = __float2bfloat16(v);
                    else if (cc < 32) { out2[(size_t)row * 16 + cc - 16] = v;
                                        dtr[(size_t)row * 32 + cc] = __float2bfloat16(0.f); }
                    else if (cc < 48) out3[(size_t)row * 16 + cc - 32] = v;
                }
            }
        } else if (OUTMODE == 2) {
            float* out = (float*)outp;
            int bI = m0 / LIMG, l0 = m0 % LIMG;
#pragma unroll
            for (int i = 0; i < 32; i++) {
                int idx = (i << 8) + tid;
                int rw = idx & 127, col = idx >> 7;
                float v = stg[rw * 65 + col] + bias[n0 + (h << 6) + col];
                size_t o = (size_t)(bI * N + n0 + (h << 6) + col) * LIMG + l0 + rw;
                out[o] = v + resid[o];
            }
        } else {
#pragma unroll
            for (int i = 0; i < 32; i++) {
                int idx = (i << 8) + tid;
                int cc = idx & 63, rw = idx >> 6;
                float v = stg[rw * 65 + cc];
                int col = n0 + (h << 6) + cc;
                if (OUTMODE == 3) {
                    float s = v + bias[col];
                    v = (s > 20.f) ? s : log1pf(expf(s));
                    ((__nv_bfloat16*)outp)[(size_t)(m0 + rw) * N + col] = __float2bfloat16(v);
                } else {
                    if (bias) v += bias[col];
                    if (OUTMODE == 1)
                        ((__nv_bfloat16*)outp)[(size_t)(m0 + rw) * N + col] = __float2bfloat16(v);
                    else
                        ((float*)outp)[(size_t)(m0 + rw) * N + col] = v;
                }
            }
        }
        __syncthreads();
    }
}

// ================= single fused weight-prep kernel =================
#define S_WB1  (CDIM*CDIM)
#define S_WBIN (2*DI*CDIM)
#define S_WBO  (CDIM*DI)
#define S_WB2  (CDIM*CDIM)
#define S_WXP  (128*DI)
#define S_WDT  (DI*32)
#define PREP_TOTAL (S_WB1+S_WBIN+S_WBO+S_WB2+S_WXP+S_WDT)
__global__ void __launch_bounds__(256) prep_weights(
    const float* __restrict__ cv1_w, const float* __restrict__ in_proj_w,
    const float* __restrict__ out_proj_w, const float* __restrict__ cv2_w,
    const float* __restrict__ x_proj_w, const float* __restrict__ dt_proj_w,
    __nv_bfloat16* __restrict__ wb1, __nv_bfloat16* __restrict__ wbin,
    __nv_bfloat16* __restrict__ wbo, __nv_bfloat16* __restrict__ wb2,
    __nv_bfloat16* __restrict__ wxp, __nv_bfloat16* __restrict__ wdt)
{
    int i = blockIdx.x * 256 + threadIdx.x;
    if (i < S_WB1) { wb1[i] = __float2bfloat16(cv1_w[i]); return; }
    i -= S_WB1;
    if (i < S_WBIN) { wbin[i] = __float2bfloat16(in_proj_w[i]); return; }
    i -= S_WBIN;
    if (i < S_WBO) { wbo[i] = __float2bfloat16(out_proj_w[i]); return; }
    i -= S_WBO;
    if (i < S_WB2) { wb2[i] = __float2bfloat16(cv2_w[i]); return; }
    i -= S_WB2;
    if (i < S_WXP) {
        int r = i >> 9, c = i & 511;
        wxp[i] = __float2bfloat16(r < 48 ? x_proj_w[r * DI + c] : 0.f);
        return;
    }
    i -= S_WXP;
    if (i < S_WDT) {
        int r = i >> 5, c = i & 31;
        wdt[i] = __float2bfloat16(c < 16 ? dt_proj_w[r * DR + c] : 0.f);
    }
}

// NCHW x -> row-major bf16 [b*L + l][c]
__global__ void __launch_bounds__(256) xpose(const float* __restrict__ x,
                                             __nv_bfloat16* __restrict__ xT)
{
    __shared__ float t[32][33];
    int l0 = blockIdx.x << 5, c0 = blockIdx.y << 5, b = blockIdx.z;
    int tx = threadIdx.x, ty = threadIdx.y;
#pragma unroll
    for (int j = 0; j < 32; j += 8)
        t[ty + j][tx] = x[((size_t)(b * CDIM + c0 + ty + j)) * LIMG + l0 + tx];
    __syncthreads();
#pragma unroll
    for (int j = 0; j < 32; j += 8)
        xT[((size_t)(b * LIMG + l0 + ty + j)) * CDIM + c0 + tx] = __float2bfloat16(t[tx][ty + j]);
}

// ================= LayerNorm: warp per row, vectorized =================
__global__ void __launch_bounds__(256) ln_kernel(
    const __nv_bfloat16* __restrict__ t0, __nv_bfloat16* __restrict__ t0b,
    const float* __restrict__ gam, const float* __restrict__ bet)
{
    int wid  = threadIdx.x >> 5, lane = threadIdx.x & 31;
    int m    = blockIdx.x * 8 + wid;
    const __nv_bfloat16* row = t0 + (size_t)m * CDIM + lane * 8;
    uint4 pk = *(const uint4*)row;
    __nv_bfloat16 vb[8];
    *(uint4*)vb = pk;
    float v[8], s1 = 0.f, s2 = 0.f;
#pragma unroll
    for (int j = 0; j < 8; j++) {
        v[j] = __bfloat162float(vb[j]);
        s1 += v[j];
        s2 += v[j] * v[j];
    }
#pragma unroll
    for (int off = 16; off; off >>= 1) {
        s1 += __shfl_xor_sync(0xffffffffu, s1, off);
        s2 += __shfl_xor_sync(0xffffffffu, s2, off);
    }
    float mu = s1 * (1.f / CDIM);
    float rs = rsqrtf(s2 * (1.f / CDIM) - mu * mu + 1e-5f);
    float4 g0 = *(const float4*)(gam + lane * 8);
    float4 g1 = *(const float4*)(gam + lane * 8 + 4);
    float4 b0 = *(const float4*)(bet + lane * 8);
    float4 b1 = *(const float4*)(bet + lane * 8 + 4);
    float gg[8] = {g0.x, g0.y, g0.z, g0.w, g1.x, g1.y, g1.z, g1.w};
    float bb[8] = {b0.x, b0.y, b0.z, b0.w, b1.x, b1.y, b1.z, b1.w};
    __nv_bfloat16 ob[8];
#pragma unroll
    for (int j = 0; j < 8; j++)
        ob[j] = __float2bfloat16((v[j] - mu) * rs * gg[j] + bb[j]);
    *(uint4*)(t0b + (size_t)m * CDIM + lane * 8) = *(uint4*)ob;
}

// ================= sliding-window depthwise conv + SiLU =================
#define CLSEG 64
__global__ void __launch_bounds__(512) conv_silu_kernel(
    const __nv_bfloat16* __restrict__ xz, const float* __restrict__ cw,
    const float* __restrict__ cb, __nv_bfloat16* __restrict__ ub)
{
    int b = blockIdx.y, d = threadIdx.x;
    int l0 = blockIdx.x * CLSEG;
    float w0 = cw[d * 4 + 0], w1 = cw[d * 4 + 1], w2 = cw[d * 4 + 2], w3 = cw[d * 4 + 3];
    float bia = cb[d];
    size_t rb = (size_t)(b * LIMG) * (2 * DI) + d;
    float x0 = (l0 >= 3) ? __bfloat162float(xz[rb + (size_t)(l0 - 3) * (2 * DI)]) : 0.f;
    float x1 = (l0 >= 2) ? __bfloat162float(xz[rb + (size_t)(l0 - 2) * (2 * DI)]) : 0.f;
    float x2 = (l0 >= 1) ? __bfloat162float(xz[rb + (size_t)(l0 - 1) * (2 * DI)]) : 0.f;
    for (int i = 0; i < CLSEG; i++) {
        float x3 = __bfloat162float(xz[rb + (size_t)(l0 + i) * (2 * DI)]);
        float s = bia + w0 * x0 + w1 * x1 + w2 * x2 + w3 * x3;
        float sig = 1.f / (1.f + __expf(-s));
        ub[(size_t)(b * LIMG + l0 + i) * DI + d] = __float2bfloat16(s * sig);
        x0 = x1; x1 = x2; x2 = x3;
    }
}

// ================= chunked selective scan =================
__global__ void __launch_bounds__(512) scan_phase1(
    const __nv_bfloat16* __restrict__ dt, const __nv_bfloat16* __restrict__ u,
    const float* __restrict__ Bm, const float* __restrict__ A_log,
    float* __restrict__ Hc, float* __restrict__ Dc)
{
    __shared__ float Bs[TCH][DS];
    int c = blockIdx.x, b = blockIdx.y, d = threadIdx.x;
    for (int idx = d; idx < TCH * DS; idx += 512)
        Bs[idx >> 4][idx & 15] = Bm[(size_t)(b * LIMG + c * TCH) * DS + idx];
    __syncthreads();

    float A[DS], h[DS];
    bool fast = true;
#pragma unroll
    for (int n = 0; n < DS; n++) {
        A[n] = -expf(A_log[d * DS + n]);
        h[n] = 0.f;
        fast = fast && (fabsf(A[n] + (float)(n + 1)) < 1e-3f * (n + 1));
    }
    float S = 0.f;
    size_t base = (size_t)(b * LIMG + c * TCH) * DI + d;
    if (fast) {
        for (int i = 0; i < TCH; i++) {
            float dtv = __bfloat162float(dt[base + (size_t)i * DI]);
            float uv  = __bfloat162float(u [base + (size_t)i * DI]);
            float du  = dtv * uv;
            S += dtv;
            float w = __expf(-dtv), e = 1.f;
#pragma unroll
            for (int n = 0; n < DS; n++) {
                e *= w;
                h[n] = e * h[n] + du * Bs[i][n];
            }
        }
    } else {
        for (int i = 0; i < TCH; i++) {
            float dtv = __bfloat162float(dt[base + (size_t)i * DI]);
            float uv  = __bfloat162float(u [base + (size_t)i * DI]);
            float du  = dtv * uv;
            S += dtv;
#pragma unroll
            for (int n = 0; n < DS; n++)
                h[n] = __expf(dtv * A[n]) * h[n] + du * Bs[i][n];
        }
    }
    size_t o = ((size_t)(b * DI + d) * NCHUNK + c) * DS;
#pragma unroll
    for (int n = 0; n < DS; n++) Hc[o + n] = h[n];
    Dc[(b * DI + d) * NCHUNK + c] = S;
}

// phase2: Kogge-Stone warp scan over chunks; one warp per (b,d,n), 2 chunks/lane
__global__ void __launch_bounds__(256) scan_phase2(
    const float* __restrict__ Hc, const float* __restrict__ Dc,
    const float* __restrict__ A_log, float* __restrict__ hstart)
{
    int gwarp = (blockIdx.x * 256 + threadIdx.x) >> 5;   // 0..16383 = (b*DI+d)*DS+n
    int lane  = threadIdx.x & 31;
    int n     = gwarp & (DS - 1);
    int d     = (gwarp >> 4) & (DI - 1);
    int b     = gwarp >> 13;
    float An  = -expf(A_log[d * DS + n]);
    size_t bb = (size_t)(b * DI + d) * NCHUNK;
    int c0 = lane * 2, c1 = c0 + 1;
    float D0 = Dc[bb + c0], D1 = Dc[bb + c1];
    float H0 = Hc[(bb + c0) * DS + n], H1 = Hc[(bb + c1) * DS + n];
    float a0 = __expf(An * D0), a1 = __expf(An * D1);
    // in-lane pair compose (chunk c0 then c1)
    float pa = a0 * a1;
    float pb = H1 + a1 * H0;
    // inclusive Kogge-Stone across lanes
#pragma unroll
    for (int off = 1; off < 32; off <<= 1) {
        float qa = __shfl_up_sync(0xffffffffu, pa, off);
        float qb = __shfl_up_sync(0xffffffffu, pb, off);
        if (lane >= off) { pb = pb + pa * qb; pa = pa * qa; }
    }
    // exclusive prefix for this lane's first chunk
    float eb = __shfl_up_sync(0xffffffffu, pb, 1);
    if (lane == 0) eb = 0.f;
    hstart[(bb + c0) * DS + n] = eb;
    hstart[(bb + c1) * DS + n] = a0 * eb + H0;
}

__global__ void __launch_bounds__(512) scan_phase3(
    const __nv_bfloat16* __restrict__ dt, const __nv_bfloat16* __restrict__ u,
    const float* __restrict__ Bm, const float* __restrict__ Cm,
    const float* __restrict__ A_log, const float* __restrict__ Dpar,
    const __nv_bfloat16* __restrict__ xz, const float* __restrict__ hstart,
    __nv_bfloat16* __restrict__ yb)
{
    __shared__ float Bs[TCH][DS], Cs[TCH][DS];
    int c = blockIdx.x, b = blockIdx.y, d = threadIdx.x;
    for (int idx = d; idx < TCH * DS; idx += 512) {
        size_t g = (size_t)(b * LIMG + c * TCH) * DS + idx;
        Bs[idx >> 4][idx & 15] = Bm[g];
        Cs[idx >> 4][idx & 15] = Cm[g];
    }
    __syncthreads();

    float A[DS], h[DS];
    bool fast = true;
    size_t ho = ((size_t)(b * DI + d) * NCHUNK + c) * DS;
#pragma unroll
    for (int n = 0; n < DS; n++) {
        A[n] = -expf(A_log[d * DS + n]);
        h[n] = hstart[ho + n];
        fast = fast && (fabsf(A[n] + (float)(n + 1)) < 1e-3f * (n + 1));
    }
    float Dd = Dpar[d];
    size_t base  = (size_t)(b * LIMG + c * TCH) * DI + d;
    size_t basez = (size_t)(b * LIMG + c * TCH) * (2 * DI) + DI + d;
    for (int i = 0; i < TCH; i++) {
        float dtv = __bfloat162float(dt[base + (size_t)i * DI]);
        float uv  = __bfloat162float(u [base + (size_t)i * DI]);
        float du  = dtv * uv;
        float acc = 0.f;
        if (fast) {
            float w = __expf(-dtv), e = 1.f;
#pragma unroll
            for (int n = 0; n < DS; n++) {
                e *= w;
                h[n] = e * h[n] + du * Bs[i][n];
                acc += h[n] * Cs[i][n];
            }
        } else {
#pragma unroll
            for (int n = 0; n < DS; n++) {
                h[n] = __expf(dtv * A[n]) * h[n] + du * Bs[i][n];
                acc += h[n] * Cs[i][n];
            }
        }
        float zv  = __bfloat162float(xz[basez + (size_t)i * (2 * DI)]);
        float sig = 1.f / (1.f + __expf(-zv));
        float yy  = (acc + uv * Dd) * (zv * sig);
        yb[base + (size_t)i * DI] = __float2bfloat16(yy);
    }
}

// ================= launch =================
extern "C" void kernel_launch(void* const* d_in, const int* in_sizes, int n_in,
                              void* d_out, int out_size)
{
    (void)in_sizes; (void)n_in; (void)out_size;
    const float* x         = (const float*)d_in[0];
    const float* cv1_w     = (const float*)d_in[1];
    const float* cv1_b     = (const float*)d_in[2];
    const float* ln_g      = (const float*)d_in[3];
    const float* ln_b      = (const float*)d_in[4];
    const float* in_proj_w = (const float*)d_in[5];
    const float* conv_w    = (const float*)d_in[6];
    const float* conv_b    = (const float*)d_in[7];
    const float* x_proj_w  = (const float*)d_in[8];
    const float* dt_proj_w = (const float*)d_in[9];
    const float* dt_proj_b = (const float*)d_in[10];
    const float* A_log     = (const float*)d_in[11];
    const float* Dp        = (const float*)d_in[12];
    const float* out_proj_w= (const float*)d_in[13];
    const float* cv2_w     = (const float*)d_in[14];
    const float* cv2_b     = (const float*)d_in[15];
    float* out = (float*)d_out;

    __nv_bfloat16 *xT, *wb1, *wbin, *wbo, *wb2, *wxp, *wdt;
    __nv_bfloat16 *t0a, *t0b, *xz, *ub, *dtr, *dtb, *yb, *t2b;
    float *Bm, *Cm, *Hc, *Dc, *hs;
    cudaGetSymbolAddress((void**)&xT,  g_xT);
    cudaGetSymbolAddress((void**)&wb1, g_wb1);
    cudaGetSymbolAddress((void**)&wbin,g_wbin);
    cudaGetSymbolAddress((void**)&wbo, g_wbo);
    cudaGetSymbolAddress((void**)&wb2, g_wb2);
    cudaGetSymbolAddress((void**)&wxp, g_wxp);
    cudaGetSymbolAddress((void**)&wdt, g_wdt);
    cudaGetSymbolAddress((void**)&t0a, g_t0a);
    cudaGetSymbolAddress((void**)&t0b, g_t0b);
    cudaGetSymbolAddress((void**)&xz,  g_xz);
    cudaGetSymbolAddress((void**)&ub,  g_ub);
    cudaGetSymbolAddress((void**)&dtr, g_dtr);
    cudaGetSymbolAddress((void**)&dtb, g_dtb);
    cudaGetSymbolAddress((void**)&Bm,  g_Bm);
    cudaGetSymbolAddress((void**)&Cm,  g_Cm);
    cudaGetSymbolAddress((void**)&Hc,  g_Hc);
    cudaGetSymbolAddress((void**)&Dc,  g_Dc);
    cudaGetSymbolAddress((void**)&hs,  g_hs);
    cudaGetSymbolAddress((void**)&yb,  g_yb);
    cudaGetSymbolAddress((void**)&t2b, g_t2b);

    prep_weights<<<(PREP_TOTAL + 255)/256, 256>>>(
        cv1_w, in_proj_w, out_proj_w, cv2_w, x_proj_w, dt_proj_w,
        wb1, wbin, wbo, wb2, wxp, wdt);
    xpose<<<dim3(LIMG/32, CDIM/32, BSZ), dim3(32, 8)>>>(x, xT);

    gemm_mma<1><<<dim3(CDIM/128, MROWS/128), 256, SMEM_BYTES>>>(
        xT, wb1, cv1_b, nullptr, t0a, nullptr, nullptr, MROWS, CDIM, CDIM);
    ln_kernel<<<MROWS/8, 256>>>(t0a, t0b, ln_g, ln_b);
    gemm_mma<1><<<dim3(2*DI/128, MROWS/128), 256, SMEM_BYTES>>>(
        t0b, wbin, nullptr, nullptr, xz, nullptr, nullptr, MROWS, 2*DI, CDIM);
    conv_silu_kernel<<<dim3(LIMG/CLSEG, BSZ), 512>>>(xz, conv_w, conv_b, ub);
    gemm_mma<4><<<dim3(1, MROWS/128), 256, SMEM_BYTES>>>(
        ub, wxp, nullptr, nullptr, dtr, Bm, Cm, MROWS, 128, DI);
    gemm_mma<3><<<dim3(DI/128, MROWS/128), 256, SMEM_BYTES>>>(
        dtr, wdt, dt_proj_b, nullptr, dtb, nullptr, nullptr, MROWS, DI, 32);
    scan_phase1<<<dim3(NCHUNK, BSZ), 512>>>(dtb, ub, Bm, A_log, Hc, Dc);
    scan_phase2<<<(BSZ*DI*DS)/8, 256>>>(Hc, Dc, A_log, hs);
    scan_phase3<<<dim3(NCHUNK, BSZ), 512>>>(dtb, ub, Bm, Cm, A_log, Dp, xz, hs, yb);
    gemm_mma<1><<<dim3(CDIM/128, MROWS/128), 256, SMEM_BYTES>>>(
        yb, wbo, nullptr, nullptr, t2b, nullptr, nullptr, MROWS, CDIM, DI);
    gemm_mma<2><<<dim3(CDIM/128, MROWS/128), 256, SMEM_BYTES>>>(
        t2b, wb2, cv2_b, x, out, nullptr, nullptr, MROWS, CDIM, CDIM);
}